// round 8
// baseline (speedup 1.0000x reference)
#include <cuda_runtime.h>
#include <cuda_bf16.h>
#include <cstddef>

// RandCropResize: tap tables + pipelined staging with a source-row register
// cache. Upsample => consecutive output rows reuse source rows; the cache
// (keyed on block-uniform row indices) turns most staging LDGs into register
// moves. Fused y-lerp keeps the main phase at 2 LDS + 2 FFMA + 1 STG/output.
// Double-buffered smem, one __syncthreads per output row, prefetch distance 1.

#define IMG_H 512
#define IMG_W 512
#define IMG_C 3
#define NROWS 16              // output rows per block
#define SPITCH 520            // smem row pitch (floats), float4-aligned

__device__ int2 g_xtab[64 * IMG_W];
__device__ int2 g_ytab[64 * IMG_H];

__global__ void __launch_bounds__(512)
setup_tables_kernel(const int* __restrict__ y1v, const int* __restrict__ y2v,
                    const int* __restrict__ x1v, const int* __restrict__ x2v)
{
    const int b = blockIdx.x;
    const int t = threadIdx.x;

    const int Y1 = y1v[b], Y2 = y2v[b];
    const int X1 = x1v[b], X2 = x2v[b];

    {   // y taps for h = t (absolute source rows)
        const int   ncy = Y2 - Y1;
        const float ny  = (float)ncy;
        float sy = ((float)t + 0.5f) * ny * (1.0f / (float)IMG_H) - 0.5f;
        sy = fminf(fmaxf(sy, 0.0f), ny - 1.0f);
        const int   iy0 = (int)floorf(sy);
        const int   iy1 = min(iy0 + 1, ncy - 1);
        const float wy  = sy - (float)iy0;
        int2 e;
        e.x = (Y1 + iy0) | ((Y1 + iy1) << 16);
        e.y = __float_as_int(wy);
        g_ytab[(b << 9) + t] = e;
    }
    {   // x taps for w = t (smem-relative: minus xlo)
        const int   xlo = X1 & ~3;
        const int   ncx = X2 - X1;
        const float nx  = (float)ncx;
        float sx = ((float)t + 0.5f) * nx * (1.0f / (float)IMG_W) - 0.5f;
        sx = fminf(fmaxf(sx, 0.0f), nx - 1.0f);
        const int   ix0 = (int)floorf(sx);
        const int   ix1 = min(ix0 + 1, ncx - 1);
        const float wx  = sx - (float)ix0;
        int2 e;
        e.x = ((X1 + ix0) - xlo) | (((X1 + ix1) - xlo) << 16);
        e.y = __float_as_int(wx);
        g_xtab[(b << 9) + t] = e;
    }
}

__global__ void __launch_bounds__(512, 4)
rand_crop_resize_kernel(const float* __restrict__ img,
                        const int* __restrict__ x1v,
                        const int* __restrict__ x2v,
                        float* __restrict__ out)
{
    __shared__ float sbuf[2][IMG_C * SPITCH];   // 2 x 6.24 KB

    const int hchunk = blockIdx.x * NROWS;
    const int b      = blockIdx.y;
    const int tid    = threadIdx.x;

    const int X1    = x1v[b];
    const int X2    = x2v[b];
    const int xlo   = X1 & ~3;
    const int span4 = (((X2 + 3) & ~3) - xlo) >> 2;   // <= 128

    const size_t img_stride = (size_t)IMG_H * IMG_W;

    // x taps: once per thread, reused for all rows
    const int2  xe = __ldg(&g_xtab[(b << 9) + tid]);
    const int   l0 = xe.x & 0xFFFF;
    const int   l1 = xe.x >> 16;
    const float wx = __int_as_float(xe.y);

    // staging role (fixed per thread)
    const int  ns     = IMG_C * span4;                // <= 384
    const bool active = tid < ns;
    const int  c      = (tid >= span4) + (tid >= 2 * span4);
    const int  xq     = tid - c * span4;
    const float* pc   = img + (size_t)b * IMG_C * img_stride
                            + (size_t)c * img_stride + xlo + (xq << 2);
    float* const sts  = &sbuf[0][c * SPITCH + (xq << 2)];
    const int    sofs = IMG_C * SPITCH;               // buffer 1 offset

    // ---- prologue: load rows of output row 0 ----
    int2 ye = __ldg(&g_ytab[(b << 9) + hchunk]);
    int   a0 = ye.x & 0xFFFF;
    int   a1 = ye.x >> 16;
    float wy = __int_as_float(ye.y);
    float4 v0 = make_float4(0.f, 0.f, 0.f, 0.f);
    float4 v1 = v0;
    if (active) {
        v0 = *(const float4*)(pc + (size_t)a0 * IMG_W);
        v1 = (a1 == a0) ? v0 : *(const float4*)(pc + (size_t)a1 * IMG_W);
    }

    float* const oblk = out + (size_t)b * IMG_C * img_stride
                            + (size_t)hchunk * IMG_W + tid;

    for (int g = 0; g < NROWS; g++) {
        const int p = g & 1;

        // ---- STS: y-lerp current row pair into sbuf[p] ----
        if (active) {
            float4 f;
            f.x = v0.x + (v1.x - v0.x) * wy;
            f.y = v0.y + (v1.y - v0.y) * wy;
            f.z = v0.z + (v1.z - v0.z) * wy;
            f.w = v0.w + (v1.w - v0.w) * wy;
            *(float4*)(sts + p * sofs) = f;
        }

        // ---- prefetch next output row, via register row-cache ----
        if (g + 1 < NROWS) {
            const int2 ye2 = __ldg(&g_ytab[(b << 9) + hchunk + g + 1]);
            const int  na0 = ye2.x & 0xFFFF;
            const int  na1 = ye2.x >> 16;
            wy = __int_as_float(ye2.y);
            // all conditions are block-uniform (a0/a1 depend only on b,h)
            float4 nv0, nv1;
            if (na0 == a0)      nv0 = v0;
            else if (na0 == a1) nv0 = v1;
            else {
                nv0 = make_float4(0.f, 0.f, 0.f, 0.f);
                if (active) nv0 = *(const float4*)(pc + (size_t)na0 * IMG_W);
            }
            if (na1 == na0)     nv1 = nv0;
            else if (na1 == a1) nv1 = v1;
            else {
                nv1 = make_float4(0.f, 0.f, 0.f, 0.f);
                if (active) nv1 = *(const float4*)(pc + (size_t)na1 * IMG_W);
            }
            v0 = nv0; v1 = nv1; a0 = na0; a1 = na1;
        }

        __syncthreads();   // one barrier per output row

        // ---- main: horizontal lerp from sbuf[p] ----
        const float* sb = &sbuf[p][0];
        float* og = oblk + (size_t)g * IMG_W;
#pragma unroll
        for (int cc = 0; cc < IMG_C; cc++) {
            const float f0 = sb[cc * SPITCH + l0];
            const float f1 = sb[cc * SPITCH + l1];
            __stcs(og + (size_t)cc * img_stride, f0 + (f1 - f0) * wx);
        }
    }
}

extern "C" void kernel_launch(void* const* d_in, const int* in_sizes, int n_in,
                              void* d_out, int out_size)
{
    const float* img = (const float*)d_in[0];
    const int*   y1  = (const int*)d_in[1];
    const int*   y2  = (const int*)d_in[2];
    const int*   x1  = (const int*)d_in[3];
    const int*   x2  = (const int*)d_in[4];
    float*       out = (float*)d_out;

    setup_tables_kernel<<<64, 512>>>(y1, y2, x1, x2);

    dim3 grid(IMG_H / NROWS, 64);   // (row chunk, b) = (32, 64)
    dim3 block(512);
    rand_crop_resize_kernel<<<grid, block>>>(img, x1, x2, out);
}